// round 2
// baseline (speedup 1.0000x reference)
#include <cuda_runtime.h>
#include <cstdint>

// ---------------------------------------------------------------------------
// DeeProBot MoE, k=1  =>  gates are one-hot argmax; softmax(top1)==1.
//   out[n] = relu(x[n] @ W1[e] + b1[e]) @ (W2[e] @ Wout) + (b2[e] @ Wout + bout)
//   e = argmax(x[n] @ w_gate),   loss = closed form of per-expert counts.
//
// Pipeline:
//   gate_fold : per-token expert + compaction into two index lists (block-
//               aggregated atomics); last block folds W2@Wout into a
//               DUPLICATED weight blob (each scalar stored as {v,v} for f32x2).
//   moe_main  : each thread = 4 tokens (2 f32x2 token-pairs) of ONE expert.
//               Weights streamed via warp-uniform LDG.128 (1 wavefront each,
//               L1-resident 12KB blob) and reused across both pairs.
//               All math in packed fma.rn.f32x2.
//   loss_kernel: closed-form loss from counts; resets counters for the next
//               graph replay (self-restoring state).
// ---------------------------------------------------------------------------

#define MAXN 524288

// dup'd weight blob: per expert e, per hidden j, 12 float2 slots:
//   0..8 = {W1[e][d][j], W1[e][d][j]},  9 = Wf0 dup, 10 = Wf1 dup, 11 = b1 dup
__device__ __align__(16) float2 g_wblob[2 * 128 * 12];
__device__ float g_bf[4];
__device__ int   g_c0 = 0, g_c1 = 0;
__device__ int   g_idx0[MAXN];
__device__ int   g_idx1[MAXN];

// ---------------- packed f32x2 helpers ----------------
__device__ __forceinline__ unsigned long long fma2(unsigned long long a,
                                                   unsigned long long b,
                                                   unsigned long long c) {
    unsigned long long d;
    asm("fma.rn.f32x2 %0, %1, %2, %3;" : "=l"(d) : "l"(a), "l"(b), "l"(c));
    return d;
}
__device__ __forceinline__ unsigned long long pack2(float a, float b) {
    unsigned long long r;
    asm("mov.b64 %0, {%1, %2};" : "=l"(r) : "f"(a), "f"(b));
    return r;
}
__device__ __forceinline__ float2 unpack2(unsigned long long v) {
    float2 r;
    asm("mov.b64 {%0, %1}, %2;" : "=f"(r.x), "=f"(r.y) : "l"(v));
    return r;
}
__device__ __forceinline__ unsigned long long relu2(unsigned long long h) {
    float2 t = unpack2(h);
    return pack2(fmaxf(t.x, 0.0f), fmaxf(t.y, 0.0f));
}

// ---------------------------------------------------------------------------
// gate_fold: blocks [0, gridDim-1) gate 256 tokens each; last block folds
// weights (and gates any remainder tokens if N % 256 != 0).
// ---------------------------------------------------------------------------
__global__ void __launch_bounds__(256) gate_fold(
        const float* __restrict__ x,  const float* __restrict__ wg,
        const float* __restrict__ W1, const float* __restrict__ b1,
        const float* __restrict__ W2, const float* __restrict__ b2,
        const float* __restrict__ Wout, const float* __restrict__ bout,
        int N) {
    const int tid = threadIdx.x;

    if (blockIdx.x == gridDim.x - 1) {
        // ---- fold: dup'd blob ----
        for (int idx = tid; idx < 3072; idx += 256) {
            int e    = idx / 1536;
            int j    = (idx / 12) & 127;
            int slot = idx % 12;
            float v;
            if (slot < 9) {
                v = W1[(e * 9 + slot) * 128 + j];
            } else if (slot < 11) {
                int o = slot - 9;
                float s = 0.0f;
                #pragma unroll
                for (int m = 0; m < 32; ++m)
                    s = fmaf(W2[(e * 128 + j) * 32 + m], Wout[m * 2 + o], s);
                v = s;
            } else {
                v = b1[e * 128 + j];
            }
            g_wblob[idx] = make_float2(v, v);
        }
        if (tid < 4) {
            int e = tid >> 1, o = tid & 1;
            float s = bout[o];
            #pragma unroll
            for (int m = 0; m < 32; ++m)
                s = fmaf(b2[e * 32 + m], Wout[m * 2 + o], s);
            g_bf[tid] = s;
        }
        // ---- remainder tokens (N % 256), scalar path ----
        int rem0 = (N / 256) * 256;
        for (int t = rem0 + tid; t < N; t += 256) {
            float l0 = 0.0f, l1 = 0.0f;
            #pragma unroll
            for (int d = 0; d < 9; ++d) {
                float v = x[(size_t)t * 9 + d];
                l0 = fmaf(v, wg[2 * d], l0);
                l1 = fmaf(v, wg[2 * d + 1], l1);
            }
            if (l1 > l0) g_idx1[atomicAdd(&g_c1, 1)] = t;
            else         g_idx0[atomicAdd(&g_c0, 1)] = t;
        }
        return;
    }

    // ---- gating for 256 tokens, staged through smem for coalescing ----
    __shared__ float sx[2304];
    __shared__ int   swc[8];       // per-warp expert-1 counts
    __shared__ int   spfx1[8];     // exclusive prefix of swc
    __shared__ int   sbase0, sbase1;

    const int tok0 = blockIdx.x * 256;
    {
        const float4* xb = reinterpret_cast<const float4*>(x + (size_t)tok0 * 9);
        float4* s4 = reinterpret_cast<float4*>(sx);
        for (int i = tid; i < 576; i += 256) s4[i] = xb[i];
    }
    float wgr[18];
    #pragma unroll
    for (int i = 0; i < 18; ++i) wgr[i] = __ldg(wg + i);
    __syncthreads();

    float l0 = 0.0f, l1 = 0.0f;
    #pragma unroll
    for (int d = 0; d < 9; ++d) {
        float v = sx[tid * 9 + d];
        l0 = fmaf(v, wgr[2 * d], l0);
        l1 = fmaf(v, wgr[2 * d + 1], l1);
    }
    const int e    = (l1 > l0) ? 1 : 0;
    const int lane = tid & 31, w = tid >> 5;

    unsigned m1 = __ballot_sync(0xffffffffu, e);
    if (lane == 0) swc[w] = __popc(m1);
    __syncthreads();
    if (tid == 0) {
        int tot1 = 0;
        #pragma unroll
        for (int i = 0; i < 8; ++i) { spfx1[i] = tot1; tot1 += swc[i]; }
        sbase1 = atomicAdd(&g_c1, tot1);
        sbase0 = atomicAdd(&g_c0, 256 - tot1);
    }
    __syncthreads();

    const int t  = tok0 + tid;
    const int r1 = __popc(m1 & ((1u << lane) - 1u));
    if (e) g_idx1[sbase1 + spfx1[w] + r1] = t;
    else   g_idx0[sbase0 + (32 * w - spfx1[w]) + (lane - r1)] = t;
}

// ---------------------------------------------------------------------------
// moe_main: thread = 4 tokens (2 token-pairs) of one expert.
// Weight rows: 6 uniform LDG.128 per hidden unit, reused by both pairs.
// ---------------------------------------------------------------------------
__global__ void __launch_bounds__(256) moe_main(const float* __restrict__ x,
                                                float* __restrict__ out) {
    const int c0 = g_c0, c1 = g_c1;
    const int u  = blockIdx.x * 256 + threadIdx.x;
    const int nb0 = (c0 + 3) >> 2;

    const int* __restrict__ list;
    int base, limit, e;
    if (u < nb0) { list = g_idx0; base = u * 4;          limit = c0; e = 0; }
    else         { list = g_idx1; base = (u - nb0) * 4;  limit = c1; e = 1; }
    if (base >= limit) return;

    // gather 4 tokens' features as token-pair f32x2
    int tk[4];
    unsigned long long x2[2][9];
    #pragma unroll
    for (int p = 0; p < 2; ++p) {
        int s0 = base + 2 * p;
        int q0 = min(s0,     limit - 1);
        int q1 = min(s0 + 1, limit - 1);
        int i0 = __ldg(list + q0);
        int i1 = __ldg(list + q1);
        tk[2 * p]     = i0;
        tk[2 * p + 1] = i1;
        const float* xa = x + (size_t)i0 * 9;
        const float* xb = x + (size_t)i1 * 9;
        #pragma unroll
        for (int d = 0; d < 9; ++d)
            x2[p][d] = pack2(__ldg(xa + d), __ldg(xb + d));
    }

    const ulonglong2* __restrict__ wb =
        reinterpret_cast<const ulonglong2*>(g_wblob) + e * 768;

    unsigned long long a00 = 0ull, a01 = 0ull;   // pair0: {t0,t1} x {o0,o1}
    unsigned long long a10 = 0ull, a11 = 0ull;   // pair1

    #pragma unroll 2
    for (int j = 0; j < 128; ++j) {
        const ulonglong2* row = wb + j * 6;
        ulonglong2 w0 = row[0], w1 = row[1], w2 = row[2];
        ulonglong2 w3 = row[3], w4 = row[4], w5 = row[5];
        // slots: w0={d0,d1} w1={d2,d3} w2={d4,d5} w3={d6,d7} w4={d8,Wf0} w5={Wf1,b1}
        {
            unsigned long long h = w5.y;
            h = fma2(x2[0][0], w0.x, h);
            h = fma2(x2[0][1], w0.y, h);
            h = fma2(x2[0][2], w1.x, h);
            h = fma2(x2[0][3], w1.y, h);
            h = fma2(x2[0][4], w2.x, h);
            h = fma2(x2[0][5], w2.y, h);
            h = fma2(x2[0][6], w3.x, h);
            h = fma2(x2[0][7], w3.y, h);
            h = fma2(x2[0][8], w4.x, h);
            h = relu2(h);
            a00 = fma2(h, w4.y, a00);
            a01 = fma2(h, w5.x, a01);
        }
        {
            unsigned long long h = w5.y;
            h = fma2(x2[1][0], w0.x, h);
            h = fma2(x2[1][1], w0.y, h);
            h = fma2(x2[1][2], w1.x, h);
            h = fma2(x2[1][3], w1.y, h);
            h = fma2(x2[1][4], w2.x, h);
            h = fma2(x2[1][5], w2.y, h);
            h = fma2(x2[1][6], w3.x, h);
            h = fma2(x2[1][7], w3.y, h);
            h = fma2(x2[1][8], w4.x, h);
            h = relu2(h);
            a10 = fma2(h, w4.y, a10);
            a11 = fma2(h, w5.x, a11);
        }
    }

    const float bf0 = g_bf[2 * e], bf1 = g_bf[2 * e + 1];
    float2* out2 = reinterpret_cast<float2*>(out);

    float2 A0 = unpack2(a00), A1 = unpack2(a01);
    if (base + 0 < limit) out2[tk[0]] = make_float2(A0.x + bf0, A1.x + bf1);
    if (base + 1 < limit) out2[tk[1]] = make_float2(A0.y + bf0, A1.y + bf1);
    float2 B0 = unpack2(a10), B1 = unpack2(a11);
    if (base + 2 < limit) out2[tk[2]] = make_float2(B0.x + bf0, B1.x + bf1);
    if (base + 3 < limit) out2[tk[3]] = make_float2(B0.y + bf0, B1.y + bf1);
}

// ---------------------------------------------------------------------------
// loss: closed-form cv^2 from expert counts; reset counters (self-restoring
// state so every graph replay starts from zero).
// ---------------------------------------------------------------------------
__global__ void loss_kernel(float* __restrict__ out, int N, int out_size) {
    if (out_size > 2 * N) {
        double c1   = (double)g_c1;
        double c0   = (double)N - c1;
        double mean = 0.5 * (c0 + c1);
        double d    = c0 - c1;
        double cv   = (0.5 * d * d) / (mean * mean + 1e-10);
        out[out_size - 1] = (float)(0.02 * cv);
    }
    g_c0 = 0;
    g_c1 = 0;
}

// ---------------------------------------------------------------------------
// Inputs: num_prop, cat_prop, w_gate, W1, b1, W2, b2, Wout, bout, k
// ---------------------------------------------------------------------------
extern "C" void kernel_launch(void* const* d_in, const int* in_sizes, int n_in,
                              void* d_out, int out_size) {
    const float* x    = (const float*)d_in[0];
    const float* wg   = (const float*)d_in[2];
    const float* W1   = (const float*)d_in[3];
    const float* b1   = (const float*)d_in[4];
    const float* W2   = (const float*)d_in[5];
    const float* b2   = (const float*)d_in[6];
    const float* Wout = (const float*)d_in[7];
    const float* bout = (const float*)d_in[8];
    float* out = (float*)d_out;

    int N = in_sizes[0] / 9;

    int gateBlocks = N / 256;              // full 256-token blocks
    gate_fold<<<gateBlocks + 1, 256>>>(x, wg, W1, b1, W2, b2, Wout, bout, N);

    int mainBlocks = (N / 4 + 2 + 255) / 256 + 1;
    moe_main<<<mainBlocks, 256>>>(x, out);

    loss_kernel<<<1, 1>>>(out, N, out_size);
}

// round 3
// speedup vs baseline: 1.4553x; 1.4553x over previous
#include <cuda_runtime.h>
#include <cstdint>

// ---------------------------------------------------------------------------
// DeeProBot MoE, k=1 => one-hot argmax gating; softmax(top1)==1.
//   out[n] = relu(x[n] @ W1[e] + b1[e]) @ (W2[e]@Wout) + (b2[e]@Wout + bout)
//   e = argmax(x[n] @ w_gate);  loss = closed form of the two expert counts.
//
// gate_kernel : 1024 tokens/block staged via float4 -> conflict-free LDS
//               (stride-9) -> 4 gates/thread -> block-aggregated compaction.
// fold_kernel : builds DUPLICATED ({v,v}) folded weight blob for f32x2.
// moe_main    : 8 tokens/thread (4 token-pairs in f32x2), lane-major gather,
//               warp-uniform weight LDG.128 amortized over 256 tokens/warp.
// loss_kernel : closed-form loss; resets counters (graph-replay safe).
// ---------------------------------------------------------------------------

#define MAXN 524288

// dup'd blob: [e][j][slot] slot0..8={W1[e][d][j]}dup, 9=Wf0 dup, 10=Wf1 dup,
// 11=b1 dup. 2*128*12 float2 = 24KB.
__device__ __align__(16) float2 g_wblob[2 * 128 * 12];
__device__ float g_bf[4];
__device__ int   g_c0 = 0, g_c1 = 0;
__device__ int   g_idx0[MAXN];
__device__ int   g_idx1[MAXN];

// ---------------- packed f32x2 helpers ----------------
__device__ __forceinline__ unsigned long long fma2(unsigned long long a,
                                                   unsigned long long b,
                                                   unsigned long long c) {
    unsigned long long d;
    asm("fma.rn.f32x2 %0, %1, %2, %3;" : "=l"(d) : "l"(a), "l"(b), "l"(c));
    return d;
}
__device__ __forceinline__ unsigned long long pack2(float a, float b) {
    unsigned long long r;
    asm("mov.b64 %0, {%1, %2};" : "=l"(r) : "f"(a), "f"(b));
    return r;
}
__device__ __forceinline__ float2 unpack2(unsigned long long v) {
    float2 r;
    asm("mov.b64 {%0, %1}, %2;" : "=f"(r.x), "=f"(r.y) : "l"(v));
    return r;
}
__device__ __forceinline__ unsigned long long relu2(unsigned long long h) {
    float2 t = unpack2(h);
    return pack2(fmaxf(t.x, 0.0f), fmaxf(t.y, 0.0f));
}

// ---------------------------------------------------------------------------
// gate_kernel: 1024 tokens per 256-thread block.
// ---------------------------------------------------------------------------
__global__ void __launch_bounds__(256) gate_kernel(const float* __restrict__ x,
                                                   const float* __restrict__ wg,
                                                   int N) {
    __shared__ float sx[9216];            // 1024 tokens * 9
    __shared__ int swc0[8], swc1[8];      // per-warp counts
    __shared__ int spf0[8], spf1[8];      // per-warp exclusive prefixes
    __shared__ int sbase0, sbase1;

    const int tid  = threadIdx.x;
    const int tok0 = blockIdx.x * 1024;
    const int navail = min(1024, N - tok0);
    const int nflt = navail * 9;

    // coalesced stage (x + tok0*9 is 16B aligned: 1024*9*4 = 36KB multiple)
    {
        const float4* xb = reinterpret_cast<const float4*>(x + (size_t)tok0 * 9);
        float4* s4 = reinterpret_cast<float4*>(sx);
        int nf4 = nflt >> 2;
        for (int i = tid; i < nf4; i += 256) s4[i] = xb[i];
        for (int i = (nf4 << 2) + tid; i < nflt; i += 256)
            sx[i] = x[(size_t)tok0 * 9 + i];
    }
    float wgr[18];
    #pragma unroll
    for (int i = 0; i < 18; ++i) wgr[i] = __ldg(wg + i);
    __syncthreads();

    const int lane = tid & 31, w = tid >> 5;
    unsigned m0[4], m1[4];

    #pragma unroll
    for (int p = 0; p < 4; ++p) {
        int tl = tid + 256 * p;           // stride-9 LDS: conflict-free
        bool valid = tl < navail;
        float l0 = 0.0f, l1 = 0.0f;
        #pragma unroll
        for (int d = 0; d < 9; ++d) {
            float v = sx[tl * 9 + d];
            l0 = fmaf(v, wgr[2 * d], l0);
            l1 = fmaf(v, wgr[2 * d + 1], l1);
        }
        bool e1 = valid && (l1 > l0);
        bool e0 = valid && !(l1 > l0);
        m1[p] = __ballot_sync(0xffffffffu, e1);
        m0[p] = __ballot_sync(0xffffffffu, e0);
    }
    if (lane == 0) {
        int c0 = 0, c1 = 0;
        #pragma unroll
        for (int p = 0; p < 4; ++p) { c0 += __popc(m0[p]); c1 += __popc(m1[p]); }
        swc0[w] = c0; swc1[w] = c1;
    }
    __syncthreads();
    if (tid == 0) {
        int t0 = 0, t1 = 0;
        #pragma unroll
        for (int i = 0; i < 8; ++i) {
            spf0[i] = t0; t0 += swc0[i];
            spf1[i] = t1; t1 += swc1[i];
        }
        sbase0 = atomicAdd(&g_c0, t0);
        sbase1 = atomicAdd(&g_c1, t1);
    }
    __syncthreads();

    int off0 = sbase0 + spf0[w];
    int off1 = sbase1 + spf1[w];
    const unsigned below = (1u << lane) - 1u;
    #pragma unroll
    for (int p = 0; p < 4; ++p) {
        int t = tok0 + tid + 256 * p;
        bool in1 = (m1[p] >> lane) & 1u;
        bool in0 = (m0[p] >> lane) & 1u;
        if (in1) g_idx1[off1 + __popc(m1[p] & below)] = t;
        if (in0) g_idx0[off0 + __popc(m0[p] & below)] = t;
        off0 += __popc(m0[p]);
        off1 += __popc(m1[p]);
    }
}

// ---------------------------------------------------------------------------
// fold_kernel: dup'd blob + folded output bias.
// ---------------------------------------------------------------------------
__global__ void __launch_bounds__(256) fold_kernel(
        const float* __restrict__ W1, const float* __restrict__ b1,
        const float* __restrict__ W2, const float* __restrict__ b2,
        const float* __restrict__ Wout, const float* __restrict__ bout) {
    const int tid = threadIdx.x;
    for (int idx = tid; idx < 3072; idx += 256) {
        int e    = idx / 1536;
        int j    = (idx / 12) & 127;
        int slot = idx % 12;
        float v;
        if (slot < 9) {
            v = W1[(e * 9 + slot) * 128 + j];
        } else if (slot < 11) {
            int o = slot - 9;
            float s = 0.0f;
            #pragma unroll
            for (int m = 0; m < 32; ++m)
                s = fmaf(W2[(e * 128 + j) * 32 + m], Wout[m * 2 + o], s);
            v = s;
        } else {
            v = b1[e * 128 + j];
        }
        g_wblob[idx] = make_float2(v, v);
    }
    if (tid < 4) {
        int e = tid >> 1, o = tid & 1;
        float s = bout[o];
        #pragma unroll
        for (int m = 0; m < 32; ++m)
            s = fmaf(b2[e * 32 + m], Wout[m * 2 + o], s);
        g_bf[tid] = s;
    }
}

// ---------------------------------------------------------------------------
// moe_main: warp = 256 tokens of one expert; thread = 8 tokens (4 f32x2
// token-pairs), lane-major so gathers are ~coalesced. Weights: warp-uniform
// LDG.128 from dup'd blob, amortized over all 8 tokens.
// ---------------------------------------------------------------------------
__global__ void __launch_bounds__(256, 2) moe_main(const float* __restrict__ x,
                                                   float* __restrict__ out) {
    const int c0 = g_c0, c1 = g_c1;
    const int W    = blockIdx.x * 8 + (threadIdx.x >> 5);
    const int lane = threadIdx.x & 31;
    const int n0   = (c0 + 255) >> 8;

    const int* __restrict__ list;
    int start, cnt, e;
    if (W < n0) { list = g_idx0; e = 0; start = W << 8;        cnt = c0; }
    else        { list = g_idx1; e = 1; start = (W - n0) << 8; cnt = c1; }
    if (start >= cnt) return;

    // gather 8 tokens as 4 token-pairs (lane-major: lanes read consecutive
    // compacted entries -> near-coalesced x rows)
    unsigned long long x2[4][9];
    #pragma unroll
    for (int q = 0; q < 4; ++q) {
        int ia = min(start + 64 * q +      lane, cnt - 1);
        int ib = min(start + 64 * q + 32 + lane, cnt - 1);
        int ta = __ldg(list + ia);
        int tb = __ldg(list + ib);
        const float* xa = x + (size_t)ta * 9;
        const float* xb = x + (size_t)tb * 9;
        #pragma unroll
        for (int d = 0; d < 9; ++d)
            x2[q][d] = pack2(__ldg(xa + d), __ldg(xb + d));
    }

    const ulonglong2* __restrict__ wb =
        reinterpret_cast<const ulonglong2*>(g_wblob) + e * 768;

    unsigned long long acc[4][2];
    #pragma unroll
    for (int q = 0; q < 4; ++q) { acc[q][0] = 0ull; acc[q][1] = 0ull; }

    #pragma unroll 2
    for (int j = 0; j < 128; ++j) {
        const ulonglong2* row = wb + j * 6;
        ulonglong2 w0 = row[0], w1 = row[1], w2 = row[2];
        ulonglong2 w3 = row[3], w4 = row[4], w5 = row[5];
        // w0={d0,d1} w1={d2,d3} w2={d4,d5} w3={d6,d7} w4={d8,Wf0} w5={Wf1,b1}
        #pragma unroll
        for (int q = 0; q < 4; ++q) {
            unsigned long long h = w5.y;            // b1 dup
            h = fma2(x2[q][0], w0.x, h);
            h = fma2(x2[q][1], w0.y, h);
            h = fma2(x2[q][2], w1.x, h);
            h = fma2(x2[q][3], w1.y, h);
            h = fma2(x2[q][4], w2.x, h);
            h = fma2(x2[q][5], w2.y, h);
            h = fma2(x2[q][6], w3.x, h);
            h = fma2(x2[q][7], w3.y, h);
            h = fma2(x2[q][8], w4.x, h);
            h = relu2(h);
            acc[q][0] = fma2(h, w4.y, acc[q][0]);   // Wf o=0
            acc[q][1] = fma2(h, w5.x, acc[q][1]);   // Wf o=1
        }
    }

    const float bf0 = g_bf[2 * e], bf1 = g_bf[2 * e + 1];
    float2* out2 = reinterpret_cast<float2*>(out);

    #pragma unroll
    for (int q = 0; q < 4; ++q) {
        float2 o0 = unpack2(acc[q][0]);   // {tA, tB} for out-dim 0
        float2 o1 = unpack2(acc[q][1]);   // {tA, tB} for out-dim 1
        int ia = start + 64 * q + lane;
        int ib = ia + 32;
        if (ia < cnt) {
            int t = __ldg(list + ia);
            out2[t] = make_float2(o0.x + bf0, o1.x + bf1);
        }
        if (ib < cnt) {
            int t = __ldg(list + ib);
            out2[t] = make_float2(o0.y + bf0, o1.y + bf1);
        }
    }
}

// ---------------------------------------------------------------------------
// loss: closed-form cv^2 from counts; reset counters for next graph replay.
// ---------------------------------------------------------------------------
__global__ void loss_kernel(float* __restrict__ out, int N, int out_size) {
    if (out_size > 2 * N) {
        double c1   = (double)g_c1;
        double c0   = (double)N - c1;
        double mean = 0.5 * (c0 + c1);
        double d    = c0 - c1;
        double cv   = (0.5 * d * d) / (mean * mean + 1e-10);
        out[out_size - 1] = (float)(0.02 * cv);
    }
    g_c0 = 0;
    g_c1 = 0;
}

// ---------------------------------------------------------------------------
// Inputs: num_prop, cat_prop, w_gate, W1, b1, W2, b2, Wout, bout, k
// ---------------------------------------------------------------------------
extern "C" void kernel_launch(void* const* d_in, const int* in_sizes, int n_in,
                              void* d_out, int out_size) {
    const float* x    = (const float*)d_in[0];
    const float* wg   = (const float*)d_in[2];
    const float* W1   = (const float*)d_in[3];
    const float* b1   = (const float*)d_in[4];
    const float* W2   = (const float*)d_in[5];
    const float* b2   = (const float*)d_in[6];
    const float* Wout = (const float*)d_in[7];
    const float* bout = (const float*)d_in[8];
    float* out = (float*)d_out;

    int N = in_sizes[0] / 9;

    fold_kernel<<<1, 256>>>(W1, b1, W2, b2, Wout, bout);
    gate_kernel<<<(N + 1023) / 1024, 256>>>(x, wg, N);

    int warpsNeeded = (N + 255) / 256 + 2;
    moe_main<<<(warpsNeeded + 7) / 8, 256>>>(x, out);

    loss_kernel<<<1, 1>>>(out, N, out_size);
}